// round 1
// baseline (speedup 1.0000x reference)
#include <cuda_runtime.h>

// Problem constants (fixed by setup_inputs)
#define NB 64
#define NA 3
#define NH 128
#define NW 128
#define HW (NH * NW)              // 16384
#define PAIRS (NB * NA * NH * (NW / 2))   // 1,572,864
#define ANGLE_RANGE 360.0f

__device__ __forceinline__ float fsigmoid(float x) {
    // fast sigmoid: MUFU.EX2-based expf + fast divide; rel err ~1e-6, fine for 1e-3 tol
    return __fdividef(1.0f, 1.0f + __expf(-x));
}

__global__ __launch_bounds__(256) void rapid_decode_kernel(
    const float* __restrict__ raw,
    const float* __restrict__ anchors,
    const int* __restrict__ img_h_p,
    const int* __restrict__ img_w_p,
    float* __restrict__ out)
{
    int t = blockIdx.x * blockDim.x + threadIdx.x;
    if (t >= PAIRS) return;

    // decode (b, a, h, w-pair)
    int w2 = t & 63;            // pair index along W (NW/2 = 64)
    int h  = (t >> 6) & 127;
    int ba = t >> 13;           // 0..191 = b*3 + a
    int a  = ba % 3;
    int b  = ba / 3;
    int w0 = w2 * 2;

    float img_w = (float)__ldg(img_w_p);
    float img_h = (float)__ldg(img_h_p);
    float sx = img_w * (1.0f / (float)NW);   // 8.0
    float sy = img_h * (1.0f / (float)NH);   // 8.0
    float aw = __ldg(anchors + 2 * a);
    float ah = __ldg(anchors + 2 * a + 1);

    // input: channel c at raw[((b*18 + a*6 + c)*NH + h)*NW + w]
    const float* p = raw + ((size_t)(b * 18 + a * 6) * HW) + h * NW + w0;
    float2 v0 = *(const float2*)(p + 0 * HW);  // tx
    float2 v1 = *(const float2*)(p + 1 * HW);  // ty
    float2 v2 = *(const float2*)(p + 2 * HW);  // tw
    float2 v3 = *(const float2*)(p + 3 * HW);  // th
    float2 v4 = *(const float2*)(p + 4 * HW);  // angle
    float2 v5 = *(const float2*)(p + 5 * HW);  // conf

    float yf = (float)h;

    // position 0
    float px0 = (fsigmoid(v0.x) + (float)(w0 + 0)) * sx;
    float py0 = (fsigmoid(v1.x) + yf) * sy;
    float pw0 = __expf(v2.x) * aw;
    float ph0 = __expf(v3.x) * ah;
    float pa0 = fsigmoid(v4.x) * ANGLE_RANGE - ANGLE_RANGE * 0.5f;
    float pc0 = fsigmoid(v5.x);

    // position 1
    float px1 = (fsigmoid(v0.y) + (float)(w0 + 1)) * sx;
    float py1 = (fsigmoid(v1.y) + yf) * sy;
    float pw1 = __expf(v2.y) * aw;
    float ph1 = __expf(v3.y) * ah;
    float pa1 = fsigmoid(v4.y) * ANGLE_RANGE - ANGLE_RANGE * 0.5f;
    float pc1 = fsigmoid(v5.y);

    // output: out[(((b*3+a)*NH + h)*NW + w)*6 + c], pair base = 12 floats = 48B aligned
    size_t pos0 = ((size_t)ba * NH + h) * NW + w0;
    float4* o = (float4*)(out + pos0 * 6);
    o[0] = make_float4(px0, py0, pw0, ph0);
    o[1] = make_float4(pa0, pc0, px1, py1);
    o[2] = make_float4(pw1, ph1, pa1, pc1);
}

extern "C" void kernel_launch(void* const* d_in, const int* in_sizes, int n_in,
                              void* d_out, int out_size) {
    const float* raw     = (const float*)d_in[0];
    const float* anchors = (const float*)d_in[1];
    const int*   img_h   = (const int*)d_in[2];
    const int*   img_w   = (const int*)d_in[3];
    float* out = (float*)d_out;

    const int threads = 256;
    const int blocks = (PAIRS + threads - 1) / threads;  // 6144
    rapid_decode_kernel<<<blocks, threads>>>(raw, anchors, img_h, img_w, out);
}